// round 1
// baseline (speedup 1.0000x reference)
#include <cuda_runtime.h>
#include <math.h>

#define DM   1024
#define NH   16
#define HD   64
#define SEQ  2048
#define NB   4
#define MTOT (NB * SEQ)   // 8192

// ---------------- scratch (device globals: allocation-free rule) ------------
__device__ float g_q[(size_t)NB * NH * SEQ * HD];   // [B,H,T,Dh]
__device__ float g_k[(size_t)NB * NH * SEQ * HD];
__device__ float g_v[(size_t)NB * NH * SEQ * HD];
__device__ float g_ao[(size_t)MTOT * DM];           // attention out, [B*T, D]

// ---------------- tiled fp32 GEMM: 128x128x16, 8x8/thread, 256 thr ---------
#define GBM 128
#define GBN 128
#define GBK 16

template <bool BHTD>
__device__ __forceinline__ void sgemm_tile(const float* __restrict__ A,
                                           const float* __restrict__ B,
                                           float* __restrict__ C,
                                           int M, int N, int K) {
    __shared__ float As[GBK][GBM + 4];
    __shared__ float Bs[GBK][GBN + 4];

    const int tid = threadIdx.x;      // 0..255
    const int tx = tid & 15;
    const int ty = tid >> 4;
    const int row0 = blockIdx.y * GBM;
    const int col0 = blockIdx.x * GBN;

    float acc[8][8];
#pragma unroll
    for (int i = 0; i < 8; i++)
#pragma unroll
        for (int j = 0; j < 8; j++) acc[i][j] = 0.f;

    for (int k0 = 0; k0 < K; k0 += GBK) {
#pragma unroll
        for (int l = 0; l < 2; l++) {
            int f = tid + l * 256;                 // 0..511 (float4 ids)
            int ar = f >> 2;                       // 0..127
            int ac = (f & 3) << 2;                 // 0,4,8,12
            float4 va = *reinterpret_cast<const float4*>(
                A + (size_t)(row0 + ar) * K + k0 + ac);
            As[ac + 0][ar] = va.x;
            As[ac + 1][ar] = va.y;
            As[ac + 2][ar] = va.z;
            As[ac + 3][ar] = va.w;
            int br = f >> 5;                       // 0..15
            int bc = (f & 31) << 2;                // 0..124
            float4 vb = *reinterpret_cast<const float4*>(
                B + (size_t)(k0 + br) * N + col0 + bc);
            *reinterpret_cast<float4*>(&Bs[br][bc]) = vb;
        }
        __syncthreads();

#pragma unroll
        for (int k = 0; k < GBK; k++) {
            float ar_[8], br_[8];
            float4 a0 = *reinterpret_cast<const float4*>(&As[k][ty * 8 + 0]);
            float4 a1 = *reinterpret_cast<const float4*>(&As[k][ty * 8 + 4]);
            ar_[0] = a0.x; ar_[1] = a0.y; ar_[2] = a0.z; ar_[3] = a0.w;
            ar_[4] = a1.x; ar_[5] = a1.y; ar_[6] = a1.z; ar_[7] = a1.w;
            float4 b0 = *reinterpret_cast<const float4*>(&Bs[k][tx * 8 + 0]);
            float4 b1 = *reinterpret_cast<const float4*>(&Bs[k][tx * 8 + 4]);
            br_[0] = b0.x; br_[1] = b0.y; br_[2] = b0.z; br_[3] = b0.w;
            br_[4] = b1.x; br_[5] = b1.y; br_[6] = b1.z; br_[7] = b1.w;
#pragma unroll
            for (int i = 0; i < 8; i++)
#pragma unroll
                for (int j = 0; j < 8; j++)
                    acc[i][j] += ar_[i] * br_[j];
        }
        __syncthreads();
    }

#pragma unroll
    for (int i = 0; i < 8; i++) {
        int m = row0 + ty * 8 + i;
#pragma unroll
        for (int j4 = 0; j4 < 2; j4++) {
            int n = col0 + tx * 8 + j4 * 4;
            float4 v = make_float4(acc[i][j4 * 4 + 0], acc[i][j4 * 4 + 1],
                                   acc[i][j4 * 4 + 2], acc[i][j4 * 4 + 3]);
            if (BHTD) {
                int b = m >> 11;            // /SEQ
                int t = m & (SEQ - 1);
                int h = n >> 6;             // /HD
                int dh = n & (HD - 1);
                size_t idx = ((size_t)(b * NH + h) * SEQ + t) * HD + dh;
                *reinterpret_cast<float4*>(C + idx) = v;
            } else {
                *reinterpret_cast<float4*>(C + (size_t)m * N + n) = v;
            }
        }
    }
}

__global__ void __launch_bounds__(256)
qkv_kernel(const float* __restrict__ qin, const float* __restrict__ kin,
           const float* __restrict__ vin, const float* __restrict__ Wq,
           const float* __restrict__ Wk, const float* __restrict__ Wv) {
    const float* A;
    const float* B;
    float* C;
    if (blockIdx.z == 0)      { A = qin; B = Wq; C = g_q; }
    else if (blockIdx.z == 1) { A = kin; B = Wk; C = g_k; }
    else                      { A = vin; B = Wv; C = g_v; }
    sgemm_tile<true>(A, B, C, MTOT, DM, DM);
}

__global__ void __launch_bounds__(256)
oproj_kernel(const float* __restrict__ Wo, float* __restrict__ out) {
    sgemm_tile<false>(g_ao, Wo, out, MTOT, DM, DM);
}

// ---------------- flash attention, fp32, Br=Bc=64 ---------------------------
#define FA_PAD 68   // smem row stride (words) for K/P and V, kills bank conflicts

__global__ void __launch_bounds__(256)
flash_kernel(const int* __restrict__ qpm, const int* __restrict__ kpm) {
    extern __shared__ float sm[];
    float* Qs = sm;                    // [64][FA_PAD]
    float* Ks = sm + 64 * FA_PAD;      // [64][FA_PAD]  (reused as P)
    float* Vs = sm + 2 * 64 * FA_PAD;  // [64][FA_PAD]
    __shared__ int kps[64];

    const int tid = threadIdx.x;
    const int sx = tid & 15;
    const int sy = tid >> 4;
    const int qt = gridDim.x - 1 - blockIdx.x;   // longest blocks first
    const int bh = blockIdx.y;
    const int b = bh >> 4;                       // / NH
    const int h = bh & (NH - 1);
    const size_t base = (size_t)bh * SEQ * HD;
    const int qrow0 = qt * 64;

    // load Q tile (64x64)
#pragma unroll
    for (int l = 0; l < 4; l++) {
        int f = tid + l * 256;
        int r = f >> 4;
        int c = (f & 15) << 2;
        float4 v = *reinterpret_cast<const float4*>(
            g_q + base + (size_t)(qrow0 + r) * HD + c);
        *reinterpret_cast<float4*>(&Qs[r * FA_PAD + c]) = v;
    }

    float m_i[4], l_i[4];
    float o_acc[4][4];
#pragma unroll
    for (int i = 0; i < 4; i++) {
        m_i[i] = -1e30f;
        l_i[i] = 0.f;
#pragma unroll
        for (int j = 0; j < 4; j++) o_acc[i][j] = 0.f;
    }

    const float scale = 0.125f;  // 1/sqrt(64)

    for (int kt = 0; kt <= qt; kt++) {
        __syncthreads();  // prev-iter P/V reads done; Q stores done (iter 0)
        const int krow0 = kt * 64;
#pragma unroll
        for (int l = 0; l < 4; l++) {
            int f = tid + l * 256;
            int r = f >> 4;
            int c = (f & 15) << 2;
            float4 kv = *reinterpret_cast<const float4*>(
                g_k + base + (size_t)(krow0 + r) * HD + c);
            *reinterpret_cast<float4*>(&Ks[r * FA_PAD + c]) = kv;
            float4 vv = *reinterpret_cast<const float4*>(
                g_v + base + (size_t)(krow0 + r) * HD + c);
            *reinterpret_cast<float4*>(&Vs[r * FA_PAD + c]) = vv;
        }
        if (tid < 64) kps[tid] = kpm[b * SEQ + krow0 + tid];
        __syncthreads();

        // S = Q K^T ; thread rows ri = sy*4+i, cols cj = sx + 16*j (strided)
        float s[4][4];
#pragma unroll
        for (int i = 0; i < 4; i++)
#pragma unroll
            for (int j = 0; j < 4; j++) s[i][j] = 0.f;

#pragma unroll
        for (int d = 0; d < HD; d += 4) {
            float4 q4[4], k4[4];
#pragma unroll
            for (int i = 0; i < 4; i++)
                q4[i] = *reinterpret_cast<const float4*>(
                    &Qs[(sy * 4 + i) * FA_PAD + d]);
#pragma unroll
            for (int j = 0; j < 4; j++)
                k4[j] = *reinterpret_cast<const float4*>(
                    &Ks[(sx + 16 * j) * FA_PAD + d]);
#pragma unroll
            for (int i = 0; i < 4; i++)
#pragma unroll
                for (int j = 0; j < 4; j++)
                    s[i][j] += q4[i].x * k4[j].x + q4[i].y * k4[j].y +
                               q4[i].z * k4[j].z + q4[i].w * k4[j].w;
        }

        // mask + scale
#pragma unroll
        for (int i = 0; i < 4; i++) {
            int gr = qrow0 + sy * 4 + i;
#pragma unroll
            for (int j = 0; j < 4; j++) {
                int gc = krow0 + sx + 16 * j;
                bool ok = (gc <= gr) && (kps[sx + 16 * j] != 0);
                s[i][j] = ok ? s[i][j] * scale : -1e30f;
            }
        }

        // online softmax update (row spread over the 16 sx lanes)
#pragma unroll
        for (int i = 0; i < 4; i++) {
            float mx = fmaxf(fmaxf(s[i][0], s[i][1]), fmaxf(s[i][2], s[i][3]));
#pragma unroll
            for (int off = 1; off < 16; off <<= 1)
                mx = fmaxf(mx, __shfl_xor_sync(0xffffffffu, mx, off));
            float mnew = fmaxf(m_i[i], mx);
            float corr = __expf(m_i[i] - mnew);
            m_i[i] = mnew;
            float rsum = 0.f;
#pragma unroll
            for (int j = 0; j < 4; j++) {
                float p = __expf(s[i][j] - mnew);
                s[i][j] = p;
                rsum += p;
            }
#pragma unroll
            for (int off = 1; off < 16; off <<= 1)
                rsum += __shfl_xor_sync(0xffffffffu, rsum, off);
            l_i[i] = l_i[i] * corr + rsum;
#pragma unroll
            for (int j = 0; j < 4; j++) o_acc[i][j] *= corr;
        }

        __syncthreads();  // all Ks reads done before overwriting with P
        float* Ps = Ks;
#pragma unroll
        for (int i = 0; i < 4; i++)
#pragma unroll
            for (int j = 0; j < 4; j++)
                Ps[(sy * 4 + i) * FA_PAD + sx + 16 * j] = s[i][j];
        __syncthreads();

        // O += P V ; thread O cols dj = sx*4 + j (consecutive)
#pragma unroll
        for (int c = 0; c < 64; c += 4) {
            float4 p4[4], v4[4];
#pragma unroll
            for (int i = 0; i < 4; i++)
                p4[i] = *reinterpret_cast<const float4*>(
                    &Ps[(sy * 4 + i) * FA_PAD + c]);
#pragma unroll
            for (int cc = 0; cc < 4; cc++)
                v4[cc] = *reinterpret_cast<const float4*>(
                    &Vs[(c + cc) * FA_PAD + sx * 4]);
#pragma unroll
            for (int i = 0; i < 4; i++) {
                const float* pr = reinterpret_cast<const float*>(&p4[i]);
#pragma unroll
                for (int cc = 0; cc < 4; cc++) {
                    float pv = pr[cc];
                    o_acc[i][0] += pv * v4[cc].x;
                    o_acc[i][1] += pv * v4[cc].y;
                    o_acc[i][2] += pv * v4[cc].z;
                    o_acc[i][3] += pv * v4[cc].w;
                }
            }
        }
    }

    // epilogue: divide by l, apply query padding, write to [B*T, D] layout
#pragma unroll
    for (int i = 0; i < 4; i++) {
        int gr = qrow0 + sy * 4 + i;
        float inv = (l_i[i] > 0.f) ? 1.0f / l_i[i] : 0.f;
        float f = inv * (float)qpm[b * SEQ + gr];
        float4 v = make_float4(o_acc[i][0] * f, o_acc[i][1] * f,
                               o_acc[i][2] * f, o_acc[i][3] * f);
        *reinterpret_cast<float4*>(
            &g_ao[(size_t)(b * SEQ + gr) * DM + h * HD + sx * 4]) = v;
    }
}

// ---------------- launch -----------------------------------------------------
extern "C" void kernel_launch(void* const* d_in, const int* in_sizes, int n_in,
                              void* d_out, int out_size) {
    const float* q   = (const float*)d_in[0];
    const float* k   = (const float*)d_in[1];
    const float* v   = (const float*)d_in[2];
    const int*   qpm = (const int*)d_in[3];
    const int*   kpm = (const int*)d_in[4];
    const float* Wq  = (const float*)d_in[5];
    const float* Wk  = (const float*)d_in[6];
    const float* Wv  = (const float*)d_in[7];
    const float* Wo  = (const float*)d_in[8];
    float* out = (float*)d_out;

    dim3 gq(DM / GBN, MTOT / GBM, 3);
    qkv_kernel<<<gq, 256>>>(q, k, v, Wq, Wk, Wv);

    const int fa_smem = 3 * 64 * FA_PAD * (int)sizeof(float);  // 52224 B
    cudaFuncSetAttribute(flash_kernel,
                         cudaFuncAttributeMaxDynamicSharedMemorySize, fa_smem);
    dim3 gf(SEQ / 64, NB * NH);
    flash_kernel<<<gf, 256, fa_smem>>>(qpm, kpm);

    dim3 go(DM / GBN, MTOT / GBM);
    oproj_kernel<<<go, 256>>>(Wo, out);
}

// round 4
// speedup vs baseline: 1.4271x; 1.4271x over previous
#include <cuda_runtime.h>
#include <cuda_bf16.h>
#include <cstdint>
#include <math.h>

#define DM   1024
#define NH   16
#define HD   64
#define SEQ  2048
#define NB   4
#define MTOT (NB * SEQ)   // 8192

// ---------------- scratch (device globals: allocation-free rule) ------------
__device__ float g_q[(size_t)NB * NH * SEQ * HD];   // [B,H,T,Dh] fp32
__device__ float g_k[(size_t)NB * NH * SEQ * HD];
__device__ float g_v[(size_t)NB * NH * SEQ * HD];
__device__ float g_ao[(size_t)MTOT * DM];           // attention out, [B*T, D]

// bf16 split buffers
__device__ __nv_bfloat16 g_ah[(size_t)3 * MTOT * DM];   // q,k,v activations hi
__device__ __nv_bfloat16 g_al[(size_t)3 * MTOT * DM];   // lo
__device__ __nv_bfloat16 g_wh[(size_t)4 * DM * DM];     // W^T ([N,K] rows) hi
__device__ __nv_bfloat16 g_wl[(size_t)4 * DM * DM];
__device__ __nv_bfloat16 g_aoh[(size_t)MTOT * DM];      // attn-out hi
__device__ __nv_bfloat16 g_aol[(size_t)MTOT * DM];

// ============================ helpers =======================================
__device__ __forceinline__ uint32_t smem_u32(const void* p) {
    uint32_t a;
    asm("{ .reg .u64 t; cvta.to.shared.u64 t, %1; cvt.u32.u64 %0, t; }"
        : "=r"(a) : "l"(p));
    return a;
}
__device__ __forceinline__ void cp_async16(uint32_t s, const void* g) {
    asm volatile("cp.async.cg.shared.global [%0], [%1], 16;" :: "r"(s), "l"(g));
}
__device__ __forceinline__ void cp_commit() {
    asm volatile("cp.async.commit_group;");
}
__device__ __forceinline__ void cp_wait1() {
    asm volatile("cp.async.wait_group 1;");
}
__device__ __forceinline__ void ldsm4(uint32_t* r, uint32_t addr) {
    asm volatile("ldmatrix.sync.aligned.m8n8.x4.shared.b16 {%0,%1,%2,%3}, [%4];"
                 : "=r"(r[0]), "=r"(r[1]), "=r"(r[2]), "=r"(r[3]) : "r"(addr));
}
__device__ __forceinline__ void mma_bf16(float* d, const uint32_t* a,
                                         const uint32_t* b) {
    asm volatile(
        "mma.sync.aligned.m16n8k16.row.col.f32.bf16.bf16.f32 "
        "{%0,%1,%2,%3},{%4,%5,%6,%7},{%8,%9},{%0,%1,%2,%3};"
        : "+f"(d[0]), "+f"(d[1]), "+f"(d[2]), "+f"(d[3])
        : "r"(a[0]), "r"(a[1]), "r"(a[2]), "r"(a[3]), "r"(b[0]), "r"(b[1]));
}

// ====================== bf16x3 HMMA GEMM (128x128x32 tiles) =================
// C[M,N] = A[M,K] * B^T, B stored [N,K]; A,B given as (hi,lo) bf16 split.
#define ST_STRIDE 80                 // bytes per 32-elem bf16 row (conflict-free)
#define OP_BYTES (128 * ST_STRIDE)   // 10240
#define STAGE_BYTES (4 * OP_BYTES)   // 40960
#define GEMM_SMEM (2 * STAGE_BYTES)  // 81920

__device__ __forceinline__ void load_stage_gemm(
    char* sm, int stage, const __nv_bfloat16* __restrict__ Ah,
    const __nv_bfloat16* __restrict__ Al, const __nv_bfloat16* __restrict__ Bh,
    const __nv_bfloat16* __restrict__ Bl, int row0, int col0, int k0, int tid) {
    const __nv_bfloat16* srcs[4] = {Ah, Al, Bh, Bl};
    uint32_t sbase = smem_u32(sm) + stage * STAGE_BYTES;
#pragma unroll
    for (int t = 0; t < 8; t++) {
        int op = t >> 1;
        int c = ((t & 1) << 8) + tid;         // 0..511 (16B chunks per operand)
        int row = c >> 2, kc = c & 3;
        int rb = (op < 2) ? row0 : col0;
        const __nv_bfloat16* g = srcs[op] + (size_t)(rb + row) * DM + k0 + kc * 8;
        uint32_t s = sbase + op * OP_BYTES + row * ST_STRIDE + kc * 16;
        cp_async16(s, g);
    }
}

template <bool BHTD>
__device__ __forceinline__ void gemm_body(const __nv_bfloat16* __restrict__ Ah,
                                          const __nv_bfloat16* __restrict__ Al,
                                          const __nv_bfloat16* __restrict__ Bh,
                                          const __nv_bfloat16* __restrict__ Bl,
                                          float* __restrict__ C,
                                          int row0, int col0) {
    extern __shared__ char sm[];
    const uint32_t sb = smem_u32(sm);
    const int tid = threadIdx.x;
    const int lane = tid & 31;
    const int w = tid >> 5;
    const int wm = w & 1;       // 2 m-warps (64 rows each)
    const int wn = w >> 1;      // 4 n-warps (32 cols each)

    float acc[4][4][4];
#pragma unroll
    for (int mi = 0; mi < 4; mi++)
#pragma unroll
        for (int ni = 0; ni < 4; ni++)
#pragma unroll
            for (int e = 0; e < 4; e++) acc[mi][ni][e] = 0.f;

    // per-lane ldmatrix byte offsets (within an operand region)
    const int a_off = (wm * 64 + (lane & 15)) * ST_STRIDE + (lane >> 4) * 16;
    const int b_off = (wn * 32 + (lane & 7) + ((lane >> 4) << 3)) * ST_STRIDE +
                      ((lane >> 3) & 1) * 16;

    load_stage_gemm(sm, 0, Ah, Al, Bh, Bl, row0, col0, 0, tid);
    cp_commit();
    load_stage_gemm(sm, 1, Ah, Al, Bh, Bl, row0, col0, 32, tid);
    cp_commit();

    const int NIT = DM / 32;   // 32
    for (int i = 0; i < NIT; i++) {
        cp_wait1();
        __syncthreads();
        const int s = i & 1;
        const uint32_t sbase = sb + s * STAGE_BYTES;
#pragma unroll
        for (int ks = 0; ks < 2; ks++) {
            uint32_t ah[4][4], al[4][4], bh[8], bl[8];
            const uint32_t abase = sbase + a_off + ks * 32;
            const uint32_t bbase = sbase + 2 * OP_BYTES + b_off + ks * 32;
#pragma unroll
            for (int mi = 0; mi < 4; mi++) {
                ldsm4(ah[mi], abase + mi * 16 * ST_STRIDE);
                ldsm4(al[mi], abase + mi * 16 * ST_STRIDE + OP_BYTES);
            }
#pragma unroll
            for (int p = 0; p < 2; p++) {
                ldsm4(&bh[p * 4], bbase + p * 16 * ST_STRIDE);
                ldsm4(&bl[p * 4], bbase + p * 16 * ST_STRIDE + OP_BYTES);
            }
#pragma unroll
            for (int mi = 0; mi < 4; mi++)
#pragma unroll
                for (int ni = 0; ni < 4; ni++) {
                    const uint32_t* fh = &bh[(ni >> 1) * 4 + (ni & 1) * 2];
                    const uint32_t* fl = &bl[(ni >> 1) * 4 + (ni & 1) * 2];
                    mma_bf16(acc[mi][ni], ah[mi], fh);
                    mma_bf16(acc[mi][ni], ah[mi], fl);
                    mma_bf16(acc[mi][ni], al[mi], fh);
                }
        }
        __syncthreads();
        if (i + 2 < NIT)
            load_stage_gemm(sm, s, Ah, Al, Bh, Bl, row0, col0, (i + 2) * 32, tid);
        cp_commit();
    }

    // epilogue: direct float2 stores
    const int grp = lane >> 2;          // 0..7
    const int tig = lane & 3;           // 0..3
#pragma unroll
    for (int mi = 0; mi < 4; mi++) {
#pragma unroll
        for (int ni = 0; ni < 4; ni++) {
            int col = col0 + wn * 32 + ni * 8 + tig * 2;
            int rlo = row0 + wm * 64 + mi * 16 + grp;
            int rhi = rlo + 8;
            float2 vlo = make_float2(acc[mi][ni][0], acc[mi][ni][1]);
            float2 vhi = make_float2(acc[mi][ni][2], acc[mi][ni][3]);
            if (BHTD) {
                int h = col >> 6, dh = col & (HD - 1);
                int b0 = rlo >> 11, t0 = rlo & (SEQ - 1);
                int b1 = rhi >> 11, t1 = rhi & (SEQ - 1);
                *reinterpret_cast<float2*>(
                    C + (((size_t)(b0 * NH + h)) * SEQ + t0) * HD + dh) = vlo;
                *reinterpret_cast<float2*>(
                    C + (((size_t)(b1 * NH + h)) * SEQ + t1) * HD + dh) = vhi;
            } else {
                *reinterpret_cast<float2*>(C + (size_t)rlo * DM + col) = vlo;
                *reinterpret_cast<float2*>(C + (size_t)rhi * DM + col) = vhi;
            }
        }
    }
}

__global__ void __launch_bounds__(256)
gemm_qkv_kernel() {
    int z = blockIdx.z;
    const __nv_bfloat16* Ah = g_ah + (size_t)z * MTOT * DM;
    const __nv_bfloat16* Al = g_al + (size_t)z * MTOT * DM;
    const __nv_bfloat16* Bh = g_wh + (size_t)z * DM * DM;
    const __nv_bfloat16* Bl = g_wl + (size_t)z * DM * DM;
    float* C = (z == 0) ? g_q : (z == 1) ? g_k : g_v;
    gemm_body<true>(Ah, Al, Bh, Bl, C, blockIdx.y * 128, blockIdx.x * 128);
}

__global__ void __launch_bounds__(256)
gemm_o_kernel(float* __restrict__ out) {
    gemm_body<false>(g_aoh, g_aol, g_wh + (size_t)3 * DM * DM,
                     g_wl + (size_t)3 * DM * DM, out,
                     blockIdx.y * 128, blockIdx.x * 128);
}

// ====================== split / transpose kernels ===========================
__device__ __forceinline__ void split1(float x, __nv_bfloat16& h, __nv_bfloat16& l) {
    h = __float2bfloat16(x);
    l = __float2bfloat16(x - __bfloat162float(h));
}

__global__ void __launch_bounds__(256)
split_act_kernel(const float* __restrict__ q, const float* __restrict__ k,
                 const float* __restrict__ v) {
    int z = blockIdx.z;
    const float* src = (z == 0) ? q : (z == 1) ? k : v;
    __nv_bfloat16* hi = g_ah + (size_t)z * MTOT * DM;
    __nv_bfloat16* lo = g_al + (size_t)z * MTOT * DM;
    size_t i4 = (size_t)blockIdx.x * 256 + threadIdx.x;   // float4 index
    float4 x = reinterpret_cast<const float4*>(src)[i4];
    __nv_bfloat16 h0, l0, h1, l1, h2, l2, h3, l3;
    split1(x.x, h0, l0); split1(x.y, h1, l1);
    split1(x.z, h2, l2); split1(x.w, h3, l3);
    __nv_bfloat162* hp = reinterpret_cast<__nv_bfloat162*>(hi + i4 * 4);
    __nv_bfloat162* lp = reinterpret_cast<__nv_bfloat162*>(lo + i4 * 4);
    hp[0] = __nv_bfloat162(h0, h1); hp[1] = __nv_bfloat162(h2, h3);
    lp[0] = __nv_bfloat162(l0, l1); lp[1] = __nv_bfloat162(l2, l3);
}

__global__ void __launch_bounds__(256)
split_ao_kernel() {
    size_t i4 = (size_t)blockIdx.x * 256 + threadIdx.x;
    float4 x = reinterpret_cast<const float4*>(g_ao)[i4];
    __nv_bfloat16 h0, l0, h1, l1, h2, l2, h3, l3;
    split1(x.x, h0, l0); split1(x.y, h1, l1);
    split1(x.z, h2, l2); split1(x.w, h3, l3);
    __nv_bfloat162* hp = reinterpret_cast<__nv_bfloat162*>(g_aoh + i4 * 4);
    __nv_bfloat162* lp = reinterpret_cast<__nv_bfloat162*>(g_aol + i4 * 4);
    hp[0] = __nv_bfloat162(h0, h1); hp[1] = __nv_bfloat162(h2, h3);
    lp[0] = __nv_bfloat162(l0, l1); lp[1] = __nv_bfloat162(l2, l3);
}

// W[k][n] (row-major [in,out]) -> Wt[n][k] hi/lo
__global__ void __launch_bounds__(256)
split_w_kernel(const float* __restrict__ Wq, const float* __restrict__ Wk,
               const float* __restrict__ Wv, const float* __restrict__ Wo) {
    __shared__ float tile[32][33];
    int z = blockIdx.z;
    const float* W = (z == 0) ? Wq : (z == 1) ? Wk : (z == 2) ? Wv : Wo;
    __nv_bfloat16* th = g_wh + (size_t)z * DM * DM;
    __nv_bfloat16* tl = g_wl + (size_t)z * DM * DM;
    int tx = threadIdx.x & 31, ty = threadIdx.x >> 5;   // (32, 8)
    int k0 = blockIdx.y * 32, n0 = blockIdx.x * 32;
#pragma unroll
    for (int i = 0; i < 4; i++)
        tile[ty + i * 8][tx] = W[(size_t)(k0 + ty + i * 8) * DM + n0 + tx];
    __syncthreads();
#pragma unroll
    for (int i = 0; i < 4; i++) {
        int n = n0 + ty + i * 8;
        int k = k0 + tx;
        float x = tile[tx][ty + i * 8];
        __nv_bfloat16 h, l;
        split1(x, h, l);
        th[(size_t)n * DM + k] = h;
        tl[(size_t)n * DM + k] = l;
    }
}

// ---------------- flash attention, fp32, Br=Bc=64 (unchanged, verified) -----
#define FA_PAD 68

__global__ void __launch_bounds__(256)
flash_kernel(const int* __restrict__ qpm, const int* __restrict__ kpm) {
    extern __shared__ float smf[];
    float* Qs = smf;
    float* Ks = smf + 64 * FA_PAD;
    float* Vs = smf + 2 * 64 * FA_PAD;
    __shared__ int kps[64];

    const int tid = threadIdx.x;
    const int sx = tid & 15;
    const int sy = tid >> 4;
    const int qt = gridDim.x - 1 - blockIdx.x;
    const int bh = blockIdx.y;
    const int b = bh >> 4;
    const int h = bh & (NH - 1);
    const size_t base = (size_t)bh * SEQ * HD;
    const int qrow0 = qt * 64;

#pragma unroll
    for (int l = 0; l < 4; l++) {
        int f = tid + l * 256;
        int r = f >> 4;
        int c = (f & 15) << 2;
        float4 v = *reinterpret_cast<const float4*>(
            g_q + base + (size_t)(qrow0 + r) * HD + c);
        *reinterpret_cast<float4*>(&Qs[r * FA_PAD + c]) = v;
    }

    float m_i[4], l_i[4];
    float o_acc[4][4];
#pragma unroll
    for (int i = 0; i < 4; i++) {
        m_i[i] = -1e30f;
        l_i[i] = 0.f;
#pragma unroll
        for (int j = 0; j < 4; j++) o_acc[i][j] = 0.f;
    }

    const float scale = 0.125f;

    for (int kt = 0; kt <= qt; kt++) {
        __syncthreads();
        const int krow0 = kt * 64;
#pragma unroll
        for (int l = 0; l < 4; l++) {
            int f = tid + l * 256;
            int r = f >> 4;
            int c = (f & 15) << 2;
            float4 kv = *reinterpret_cast<const float4*>(
                g_k + base + (size_t)(krow0 + r) * HD + c);
            *reinterpret_cast<float4*>(&Ks[r * FA_PAD + c]) = kv;
            float4 vv = *reinterpret_cast<const float4*>(
                g_v + base + (size_t)(krow0 + r) * HD + c);
            *reinterpret_cast<float4*>(&Vs[r * FA_PAD + c]) = vv;
        }
        if (tid < 64) kps[tid] = kpm[b * SEQ + krow0 + tid];
        __syncthreads();

        float s[4][4];
#pragma unroll
        for (int i = 0; i < 4; i++)
#pragma unroll
            for (int j = 0; j < 4; j++) s[i][j] = 0.f;

#pragma unroll
        for (int d = 0; d < HD; d += 4) {
            float4 q4[4], k4[4];
#pragma unroll
            for (int i = 0; i < 4; i++)
                q4[i] = *reinterpret_cast<const float4*>(
                    &Qs[(sy * 4 + i) * FA_PAD + d]);
#pragma unroll
            for (int j = 0; j < 4; j++)
                k4[j] = *reinterpret_cast<const float4*>(
                    &Ks[(sx + 16 * j) * FA_PAD + d]);
#pragma unroll
            for (int i = 0; i < 4; i++)
#pragma unroll
                for (int j = 0; j < 4; j++)
                    s[i][j] += q4[i].x * k4[j].x + q4[i].y * k4[j].y +
                               q4[i].z * k4[j].z + q4[i].w * k4[j].w;
        }

#pragma unroll
        for (int i = 0; i < 4; i++) {
            int gr = qrow0 + sy * 4 + i;
#pragma unroll
            for (int j = 0; j < 4; j++) {
                int gc = krow0 + sx + 16 * j;
                bool ok = (gc <= gr) && (kps[sx + 16 * j] != 0);
                s[i][j] = ok ? s[i][j] * scale : -1e30f;
            }
        }

#pragma unroll
        for (int i = 0; i < 4; i++) {
            float mx = fmaxf(fmaxf(s[i][0], s[i][1]), fmaxf(s[i][2], s[i][3]));
#pragma unroll
            for (int off = 1; off < 16; off <<= 1)
                mx = fmaxf(mx, __shfl_xor_sync(0xffffffffu, mx, off));
            float mnew = fmaxf(m_i[i], mx);
            float corr = __expf(m_i[i] - mnew);
            m_i[i] = mnew;
            float rsum = 0.f;
#pragma unroll
            for (int j = 0; j < 4; j++) {
                float p = __expf(s[i][j] - mnew);
                s[i][j] = p;
                rsum += p;
            }
#pragma unroll
            for (int off = 1; off < 16; off <<= 1)
                rsum += __shfl_xor_sync(0xffffffffu, rsum, off);
            l_i[i] = l_i[i] * corr + rsum;
#pragma unroll
            for (int j = 0; j < 4; j++) o_acc[i][j] *= corr;
        }

        __syncthreads();
        float* Ps = Ks;
#pragma unroll
        for (int i = 0; i < 4; i++)
#pragma unroll
            for (int j = 0; j < 4; j++)
                Ps[(sy * 4 + i) * FA_PAD + sx + 16 * j] = s[i][j];
        __syncthreads();

#pragma unroll
        for (int c = 0; c < 64; c += 4) {
            float4 p4[4], v4[4];
#pragma unroll
            for (int i = 0; i < 4; i++)
                p4[i] = *reinterpret_cast<const float4*>(
                    &Ps[(sy * 4 + i) * FA_PAD + c]);
#pragma unroll
            for (int cc = 0; cc < 4; cc++)
                v4[cc] = *reinterpret_cast<const float4*>(
                    &Vs[(c + cc) * FA_PAD + sx * 4]);
#pragma unroll
            for (int i = 0; i < 4; i++) {
                const float* pr = reinterpret_cast<const float*>(&p4[i]);
#pragma unroll
                for (int cc = 0; cc < 4; cc++) {
                    float pv = pr[cc];
                    o_acc[i][0] += pv * v4[cc].x;
                    o_acc[i][1] += pv * v4[cc].y;
                    o_acc[i][2] += pv * v4[cc].z;
                    o_acc[i][3] += pv * v4[cc].w;
                }
            }
        }
    }

#pragma unroll
    for (int i = 0; i < 4; i++) {
        int gr = qrow0 + sy * 4 + i;
        float inv = (l_i[i] > 0.f) ? 1.0f / l_i[i] : 0.f;
        float f = inv * (float)qpm[b * SEQ + gr];
        float4 v = make_float4(o_acc[i][0] * f, o_acc[i][1] * f,
                               o_acc[i][2] * f, o_acc[i][3] * f);
        *reinterpret_cast<float4*>(
            &g_ao[(size_t)(b * SEQ + gr) * DM + h * HD + sx * 4]) = v;
    }
}

// ---------------- launch -----------------------------------------------------
extern "C" void kernel_launch(void* const* d_in, const int* in_sizes, int n_in,
                              void* d_out, int out_size) {
    const float* q   = (const float*)d_in[0];
    const float* k   = (const float*)d_in[1];
    const float* v   = (const float*)d_in[2];
    const int*   qpm = (const int*)d_in[3];
    const int*   kpm = (const int*)d_in[4];
    const float* Wq  = (const float*)d_in[5];
    const float* Wk  = (const float*)d_in[6];
    const float* Wv  = (const float*)d_in[7];
    const float* Wo  = (const float*)d_in[8];
    float* out = (float*)d_out;

    // 1) fp32 -> bf16 hi/lo splits
    dim3 gs((MTOT * DM) / (256 * 4), 1, 3);
    split_act_kernel<<<gs, 256>>>(q, k, v);
    split_w_kernel<<<dim3(32, 32, 4), 256>>>(Wq, Wk, Wv, Wo);

    // 2) QKV projections on HMMA tensor cores
    cudaFuncSetAttribute(gemm_qkv_kernel,
                         cudaFuncAttributeMaxDynamicSharedMemorySize, GEMM_SMEM);
    cudaFuncSetAttribute(gemm_o_kernel,
                         cudaFuncAttributeMaxDynamicSharedMemorySize, GEMM_SMEM);
    gemm_qkv_kernel<<<dim3(DM / 128, MTOT / 128, 3), 256, GEMM_SMEM>>>();

    // 3) flash attention (fp32)
    const int fa_smem = 3 * 64 * FA_PAD * (int)sizeof(float);
    cudaFuncSetAttribute(flash_kernel,
                         cudaFuncAttributeMaxDynamicSharedMemorySize, fa_smem);
    flash_kernel<<<dim3(SEQ / 64, NB * NH), 256, fa_smem>>>(qpm, kpm);

    // 4) output projection
    split_ao_kernel<<<(MTOT * DM) / (256 * 4), 256>>>();
    gemm_o_kernel<<<dim3(DM / 128, MTOT / 128), 256, GEMM_SMEM>>>(out);
}

// round 6
// speedup vs baseline: 2.0942x; 1.4674x over previous
#include <cuda_runtime.h>
#include <cuda_bf16.h>
#include <cstdint>
#include <math.h>

#define DM   1024
#define NH   16
#define HD   64
#define SEQ  2048
#define NB   4
#define MTOT (NB * SEQ)   // 8192

// ---------------- scratch (device globals: allocation-free rule) ------------
// bf16 hi/lo Q,K,V in [B,H,T,Dh]
__device__ __nv_bfloat16 g_qh[(size_t)NB * NH * SEQ * HD];
__device__ __nv_bfloat16 g_ql[(size_t)NB * NH * SEQ * HD];
__device__ __nv_bfloat16 g_kh[(size_t)NB * NH * SEQ * HD];
__device__ __nv_bfloat16 g_kl[(size_t)NB * NH * SEQ * HD];
__device__ __nv_bfloat16 g_vh[(size_t)NB * NH * SEQ * HD];
__device__ __nv_bfloat16 g_vl[(size_t)NB * NH * SEQ * HD];

// bf16 split buffers for projection inputs
__device__ __nv_bfloat16 g_ah[(size_t)3 * MTOT * DM];   // q,k,v activations hi
__device__ __nv_bfloat16 g_al[(size_t)3 * MTOT * DM];   // lo
__device__ __nv_bfloat16 g_wh[(size_t)4 * DM * DM];     // W^T ([N,K] rows) hi
__device__ __nv_bfloat16 g_wl[(size_t)4 * DM * DM];
__device__ __nv_bfloat16 g_aoh[(size_t)MTOT * DM];      // attn-out hi [B*T, D]
__device__ __nv_bfloat16 g_aol[(size_t)MTOT * DM];

// ============================ helpers =======================================
__device__ __forceinline__ uint32_t smem_u32(const void* p) {
    uint32_t a;
    asm("{ .reg .u64 t; cvta.to.shared.u64 t, %1; cvt.u32.u64 %0, t; }"
        : "=r"(a) : "l"(p));
    return a;
}
__device__ __forceinline__ void cp_async16(uint32_t s, const void* g) {
    asm volatile("cp.async.cg.shared.global [%0], [%1], 16;" :: "r"(s), "l"(g));
}
__device__ __forceinline__ void cp_commit() {
    asm volatile("cp.async.commit_group;");
}
__device__ __forceinline__ void cp_wait1() {
    asm volatile("cp.async.wait_group 1;");
}
__device__ __forceinline__ void cp_wait0() {
    asm volatile("cp.async.wait_group 0;");
}
__device__ __forceinline__ void ldsm4(uint32_t* r, uint32_t addr) {
    asm volatile("ldmatrix.sync.aligned.m8n8.x4.shared.b16 {%0,%1,%2,%3}, [%4];"
                 : "=r"(r[0]), "=r"(r[1]), "=r"(r[2]), "=r"(r[3]) : "r"(addr));
}
__device__ __forceinline__ void mma_bf16(float* d, const uint32_t* a,
                                         const uint32_t* b) {
    asm volatile(
        "mma.sync.aligned.m16n8k16.row.col.f32.bf16.bf16.f32 "
        "{%0,%1,%2,%3},{%4,%5,%6,%7},{%8,%9},{%0,%1,%2,%3};"
        : "+f"(d[0]), "+f"(d[1]), "+f"(d[2]), "+f"(d[3])
        : "r"(a[0]), "r"(a[1]), "r"(a[2]), "r"(a[3]), "r"(b[0]), "r"(b[1]));
}
// FMA-pipe exp2 (no MUFU). |err| ~3e-6 rel on reduced range [-0.5,0.5].
__device__ __forceinline__ float fexp2(float x) {
    x = fmaxf(x, -125.0f);
    int i = __float2int_rn(x);
    float f = x - (float)i;
    float p = 0.0013333558f;
    p = fmaf(p, f, 0.0096181291f);
    p = fmaf(p, f, 0.0555041087f);
    p = fmaf(p, f, 0.2402265070f);
    p = fmaf(p, f, 0.6931471806f);
    p = fmaf(p, f, 1.0f);
    return p * __int_as_float((i + 127) << 23);
}
#define LOG2E 1.4426950408889634f

__device__ __forceinline__ void split1(float x, __nv_bfloat16& h, __nv_bfloat16& l) {
    h = __float2bfloat16(x);
    l = __float2bfloat16(x - __bfloat162float(h));
}
__device__ __forceinline__ void split_pack(float a, float b, uint32_t& hw, uint32_t& lw) {
    __nv_bfloat16 ha, la, hb, lb;
    split1(a, ha, la);
    split1(b, hb, lb);
    __nv_bfloat162 h2(ha, hb), l2(la, lb);
    hw = *reinterpret_cast<uint32_t*>(&h2);
    lw = *reinterpret_cast<uint32_t*>(&l2);
}

// ====================== bf16x3 HMMA GEMM (128x128x32 tiles) =================
#define ST_STRIDE 80
#define OP_BYTES (128 * ST_STRIDE)
#define STAGE_BYTES (4 * OP_BYTES)
#define GEMM_SMEM (2 * STAGE_BYTES)

__device__ __forceinline__ void load_stage_gemm(
    char* sm, int stage, const __nv_bfloat16* __restrict__ Ah,
    const __nv_bfloat16* __restrict__ Al, const __nv_bfloat16* __restrict__ Bh,
    const __nv_bfloat16* __restrict__ Bl, int row0, int col0, int k0, int tid) {
    const __nv_bfloat16* srcs[4] = {Ah, Al, Bh, Bl};
    uint32_t sbase = smem_u32(sm) + stage * STAGE_BYTES;
#pragma unroll
    for (int t = 0; t < 8; t++) {
        int op = t >> 1;
        int c = ((t & 1) << 8) + tid;
        int row = c >> 2, kc = c & 3;
        int rb = (op < 2) ? row0 : col0;
        const __nv_bfloat16* g = srcs[op] + (size_t)(rb + row) * DM + k0 + kc * 8;
        uint32_t s = sbase + op * OP_BYTES + row * ST_STRIDE + kc * 16;
        cp_async16(s, g);
    }
}

// MODE 0: fp32 out [M,DM].  MODE 1: bf16 hi/lo out, BHTD scatter, with scale.
template <int MODE>
__device__ __forceinline__ void gemm_body(const __nv_bfloat16* __restrict__ Ah,
                                          const __nv_bfloat16* __restrict__ Al,
                                          const __nv_bfloat16* __restrict__ Bh,
                                          const __nv_bfloat16* __restrict__ Bl,
                                          float* __restrict__ Cf,
                                          __nv_bfloat16* __restrict__ Chi,
                                          __nv_bfloat16* __restrict__ Clo,
                                          float scale, int row0, int col0) {
    extern __shared__ char sm[];
    const uint32_t sb = smem_u32(sm);
    const int tid = threadIdx.x;
    const int lane = tid & 31;
    const int w = tid >> 5;
    const int wm = w & 1;
    const int wn = w >> 1;

    float acc[4][4][4];
#pragma unroll
    for (int mi = 0; mi < 4; mi++)
#pragma unroll
        for (int ni = 0; ni < 4; ni++)
#pragma unroll
            for (int e = 0; e < 4; e++) acc[mi][ni][e] = 0.f;

    const int a_off = (wm * 64 + (lane & 15)) * ST_STRIDE + (lane >> 4) * 16;
    const int b_off = (wn * 32 + (lane & 7) + ((lane >> 4) << 3)) * ST_STRIDE +
                      ((lane >> 3) & 1) * 16;

    load_stage_gemm(sm, 0, Ah, Al, Bh, Bl, row0, col0, 0, tid);
    cp_commit();
    load_stage_gemm(sm, 1, Ah, Al, Bh, Bl, row0, col0, 32, tid);
    cp_commit();

    const int NIT = DM / 32;
    for (int i = 0; i < NIT; i++) {
        cp_wait1();
        __syncthreads();
        const int s = i & 1;
        const uint32_t sbase = sb + s * STAGE_BYTES;
#pragma unroll
        for (int ks = 0; ks < 2; ks++) {
            uint32_t ah[4][4], al[4][4], bh[8], bl[8];
            const uint32_t abase = sbase + a_off + ks * 32;
            const uint32_t bbase = sbase + 2 * OP_BYTES + b_off + ks * 32;
#pragma unroll
            for (int mi = 0; mi < 4; mi++) {
                ldsm4(ah[mi], abase + mi * 16 * ST_STRIDE);
                ldsm4(al[mi], abase + mi * 16 * ST_STRIDE + OP_BYTES);
            }
#pragma unroll
            for (int p = 0; p < 2; p++) {
                ldsm4(&bh[p * 4], bbase + p * 16 * ST_STRIDE);
                ldsm4(&bl[p * 4], bbase + p * 16 * ST_STRIDE + OP_BYTES);
            }
#pragma unroll
            for (int mi = 0; mi < 4; mi++)
#pragma unroll
                for (int ni = 0; ni < 4; ni++) {
                    const uint32_t* fh = &bh[(ni >> 1) * 4 + (ni & 1) * 2];
                    const uint32_t* fl = &bl[(ni >> 1) * 4 + (ni & 1) * 2];
                    mma_bf16(acc[mi][ni], ah[mi], fh);
                    mma_bf16(acc[mi][ni], ah[mi], fl);
                    mma_bf16(acc[mi][ni], al[mi], fh);
                }
        }
        __syncthreads();
        if (i + 2 < NIT)
            load_stage_gemm(sm, s, Ah, Al, Bh, Bl, row0, col0, (i + 2) * 32, tid);
        cp_commit();
    }

    const int grp = lane >> 2;
    const int tig = lane & 3;
#pragma unroll
    for (int mi = 0; mi < 4; mi++) {
#pragma unroll
        for (int ni = 0; ni < 4; ni++) {
            int col = col0 + wn * 32 + ni * 8 + tig * 2;
            int rlo = row0 + wm * 64 + mi * 16 + grp;
            int rhi = rlo + 8;
            if (MODE == 0) {
                *reinterpret_cast<float2*>(Cf + (size_t)rlo * DM + col) =
                    make_float2(acc[mi][ni][0], acc[mi][ni][1]);
                *reinterpret_cast<float2*>(Cf + (size_t)rhi * DM + col) =
                    make_float2(acc[mi][ni][2], acc[mi][ni][3]);
            } else {
                int h = col >> 6, dh = col & (HD - 1);
                int b0 = rlo >> 11, t0 = rlo & (SEQ - 1);
                int b1 = rhi >> 11, t1 = rhi & (SEQ - 1);
                size_t i0 = (((size_t)(b0 * NH + h)) * SEQ + t0) * HD + dh;
                size_t i1 = (((size_t)(b1 * NH + h)) * SEQ + t1) * HD + dh;
                uint32_t hw, lw;
                split_pack(acc[mi][ni][0] * scale, acc[mi][ni][1] * scale, hw, lw);
                *reinterpret_cast<uint32_t*>(Chi + i0) = hw;
                *reinterpret_cast<uint32_t*>(Clo + i0) = lw;
                split_pack(acc[mi][ni][2] * scale, acc[mi][ni][3] * scale, hw, lw);
                *reinterpret_cast<uint32_t*>(Chi + i1) = hw;
                *reinterpret_cast<uint32_t*>(Clo + i1) = lw;
            }
        }
    }
}

__global__ void __launch_bounds__(256)
gemm_qkv_kernel() {
    int z = blockIdx.z;
    const __nv_bfloat16* Ah = g_ah + (size_t)z * MTOT * DM;
    const __nv_bfloat16* Al = g_al + (size_t)z * MTOT * DM;
    const __nv_bfloat16* Bh = g_wh + (size_t)z * DM * DM;
    const __nv_bfloat16* Bl = g_wl + (size_t)z * DM * DM;
    __nv_bfloat16* Chi = (z == 0) ? g_qh : (z == 1) ? g_kh : g_vh;
    __nv_bfloat16* Clo = (z == 0) ? g_ql : (z == 1) ? g_kl : g_vl;
    float scale = (z == 0) ? 0.125f : 1.0f;   // fold 1/sqrt(64) into Q
    gemm_body<1>(Ah, Al, Bh, Bl, nullptr, Chi, Clo, scale,
                 blockIdx.y * 128, blockIdx.x * 128);
}

__global__ void __launch_bounds__(256)
gemm_o_kernel(float* __restrict__ out) {
    gemm_body<0>(g_aoh, g_aol, g_wh + (size_t)3 * DM * DM,
                 g_wl + (size_t)3 * DM * DM, out, nullptr, nullptr, 1.0f,
                 blockIdx.y * 128, blockIdx.x * 128);
}

// ====================== split / transpose kernels ===========================
__global__ void __launch_bounds__(256)
split_act_kernel(const float* __restrict__ q, const float* __restrict__ k,
                 const float* __restrict__ v) {
    int z = blockIdx.z;
    const float* src = (z == 0) ? q : (z == 1) ? k : v;
    __nv_bfloat16* hi = g_ah + (size_t)z * MTOT * DM;
    __nv_bfloat16* lo = g_al + (size_t)z * MTOT * DM;
    size_t i4 = (size_t)blockIdx.x * 256 + threadIdx.x;
    float4 x = reinterpret_cast<const float4*>(src)[i4];
    uint32_t h0, l0, h1, l1;
    split_pack(x.x, x.y, h0, l0);
    split_pack(x.z, x.w, h1, l1);
    uint32_t* hp = reinterpret_cast<uint32_t*>(hi + i4 * 4);
    uint32_t* lp = reinterpret_cast<uint32_t*>(lo + i4 * 4);
    hp[0] = h0; hp[1] = h1;
    lp[0] = l0; lp[1] = l1;
}

__global__ void __launch_bounds__(256)
split_w_kernel(const float* __restrict__ Wq, const float* __restrict__ Wk,
               const float* __restrict__ Wv, const float* __restrict__ Wo) {
    __shared__ float tile[32][33];
    int z = blockIdx.z;
    const float* W = (z == 0) ? Wq : (z == 1) ? Wk : (z == 2) ? Wv : Wo;
    __nv_bfloat16* th = g_wh + (size_t)z * DM * DM;
    __nv_bfloat16* tl = g_wl + (size_t)z * DM * DM;
    int tx = threadIdx.x & 31, ty = threadIdx.x >> 5;
    int k0 = blockIdx.y * 32, n0 = blockIdx.x * 32;
#pragma unroll
    for (int i = 0; i < 4; i++)
        tile[ty + i * 8][tx] = W[(size_t)(k0 + ty + i * 8) * DM + n0 + tx];
    __syncthreads();
#pragma unroll
    for (int i = 0; i < 4; i++) {
        int n = n0 + ty + i * 8;
        int k = k0 + tx;
        __nv_bfloat16 h, l;
        split1(tile[tx][ty + i * 8], h, l);
        th[(size_t)n * DM + k] = h;
        tl[(size_t)n * DM + k] = l;
    }
}

// ====================== tensorized flash attention ==========================
// Br=128 per CTA (8 warps x 16 rows), Bc=64 per iter. All MMA hi/lo 3-term.
#define FSTR 144                      // smem row stride bytes (64 bf16 + pad)
#define FOP  (64 * FSTR)              // 9216 B per operand tile
#define FSTAGE (4 * FOP)              // Kh,Kl,Vth,Vtl
#define FBIAS_OFF (2 * FSTAGE)        // 73728
#define FLASH_SMEM (FBIAS_OFF + 2 * 64 * 4)

__global__ void __launch_bounds__(256)
flash_kernel(const int* __restrict__ qpm, const int* __restrict__ kpm) {
    extern __shared__ char sm[];
    const uint32_t sb = smem_u32(sm);
    float* biasp = reinterpret_cast<float*>(sm + FBIAS_OFF);

    const int tid = threadIdx.x;
    const int lane = tid & 31;
    const int w = tid >> 5;
    const int grp = lane >> 2;
    const int tig = lane & 3;

    const int qt = gridDim.x - 1 - blockIdx.x;       // heavy tiles first
    const int bh = blockIdx.y;
    const int b = bh >> 4;
    const int h = bh & (NH - 1);
    const size_t base = (size_t)bh * SEQ * HD;
    const int qrow0 = qt * 128;
    const int nit = 2 * qt + 2;

    // ---- load Q fragments (hi, lo), rows w*16.., pre-scaled by 1/8 ----
    uint32_t qfh[4][4], qfl[4][4];
    const int a_off = (w * 16 + (lane & 15)) * FSTR + (lane >> 4) * 16;
    {
#pragma unroll
        for (int pass = 0; pass < 2; pass++) {
            const __nv_bfloat16* src = pass == 0 ? g_qh : g_ql;
#pragma unroll
            for (int l = 0; l < 4; l++) {
                int f = tid + l * 256;          // 1024 chunks: 128 rows x 8
                int row = f >> 3, c = f & 7;
                uint4 v = *reinterpret_cast<const uint4*>(
                    src + base + (size_t)(qrow0 + row) * HD + c * 8);
                *reinterpret_cast<uint4*>(sm + row * FSTR + c * 16) = v;
            }
            __syncthreads();
#pragma unroll
            for (int kd = 0; kd < 4; kd++) {
                if (pass == 0) ldsm4(qfh[kd], sb + a_off + kd * 32);
                else           ldsm4(qfl[kd], sb + a_off + kd * 32);
            }
            __syncthreads();
        }
    }

    // ---- state ----
    float o[8][4];
#pragma unroll
    for (int ni = 0; ni < 8; ni++)
#pragma unroll
        for (int e = 0; e < 4; e++) o[ni][e] = 0.f;
    float m0 = -1e30f, m1 = -1e30f, l0 = 0.f, l1 = 0.f;

    // V ldg mapping: kv0 = (tid&31)*2, dh0 = (tid>>5)*8
    const int vkv = (tid & 31) * 2;
    const int vdh = (tid >> 5) * 8;
    uint4 pvh0, pvh1, pvl0, pvl1;   // prefetched V rows (hi kv0, hi kv0+1, lo...)

    // prefetch iter 0
    {
        const __nv_bfloat16* ph = g_vh + base + (size_t)vkv * HD + vdh;
        pvh0 = *reinterpret_cast<const uint4*>(ph);
        pvh1 = *reinterpret_cast<const uint4*>(ph + HD);
        const __nv_bfloat16* pl = g_vl + base + (size_t)vkv * HD + vdh;
        pvl0 = *reinterpret_cast<const uint4*>(pl);
        pvl1 = *reinterpret_cast<const uint4*>(pl + HD);
        // K iter0 -> stage 0
#pragma unroll
        for (int l = 0; l < 4; l++) {
            int f = tid + l * 256;
            int op = f >> 9, rem = f & 511;
            int row = rem >> 3, c = rem & 7;
            const __nv_bfloat16* g =
                (op ? g_kl : g_kh) + base + (size_t)row * HD + c * 8;
            cp_async16(sb + op * FOP + row * FSTR + c * 16, g);
        }
        cp_commit();
    }

    const int b_off = ((lane & 7) + ((lane >> 4) << 3)) * FSTR +
                      ((lane >> 3) & 1) * 16;

    for (int it = 0; it < nit; it++) {
        const int s = it & 1;
        const int krow0 = it * 64;
        const uint32_t stg = sb + s * FSTAGE;

        // STS prefetched V (transposed) into this stage
        {
            const __nv_bfloat16* h0 = reinterpret_cast<const __nv_bfloat16*>(&pvh0);
            const __nv_bfloat16* h1 = reinterpret_cast<const __nv_bfloat16*>(&pvh1);
            const __nv_bfloat16* q0 = reinterpret_cast<const __nv_bfloat16*>(&pvl0);
            const __nv_bfloat16* q1 = reinterpret_cast<const __nv_bfloat16*>(&pvl1);
#pragma unroll
            for (int j = 0; j < 8; j++) {
                uint32_t wh = (uint32_t)*reinterpret_cast<const uint16_t*>(h0 + j) |
                              ((uint32_t)*reinterpret_cast<const uint16_t*>(h1 + j) << 16);
                uint32_t wl = (uint32_t)*reinterpret_cast<const uint16_t*>(q0 + j) |
                              ((uint32_t)*reinterpret_cast<const uint16_t*>(q1 + j) << 16);
                uint32_t off = (vdh + j) * FSTR + vkv * 2;
                *reinterpret_cast<uint32_t*>(sm + s * FSTAGE + 2 * FOP + off) = wh;
                *reinterpret_cast<uint32_t*>(sm + s * FSTAGE + 3 * FOP + off) = wl;
            }
        }
        if (tid < 64)
            biasp[s * 64 + tid] =
                (kpm[b * SEQ + krow0 + tid] != 0) ? 0.f : -1e30f;

        // prefetch next iter
        if (it + 1 < nit) {
            const int nk0 = (it + 1) * 64;
            const __nv_bfloat16* ph = g_vh + base + (size_t)(nk0 + vkv) * HD + vdh;
            pvh0 = *reinterpret_cast<const uint4*>(ph);
            pvh1 = *reinterpret_cast<const uint4*>(ph + HD);
            const __nv_bfloat16* pl = g_vl + base + (size_t)(nk0 + vkv) * HD + vdh;
            pvl0 = *reinterpret_cast<const uint4*>(pl);
            pvl1 = *reinterpret_cast<const uint4*>(pl + HD);
#pragma unroll
            for (int l = 0; l < 4; l++) {
                int f = tid + l * 256;
                int op = f >> 9, rem = f & 511;
                int row = rem >> 3, c = rem & 7;
                const __nv_bfloat16* g = (op ? g_kl : g_kh) + base +
                                         (size_t)(nk0 + row) * HD + c * 8;
                cp_async16(sb + (s ^ 1) * FSTAGE + op * FOP + row * FSTR + c * 16, g);
            }
            cp_commit();
            cp_wait1();
        } else {
            cp_wait0();
        }
        __syncthreads();

        // ---- S = Q K^T (hi/lo x3) ----
        float sc[8][4];
#pragma unroll
        for (int ni = 0; ni < 8; ni++)
#pragma unroll
            for (int e = 0; e < 4; e++) sc[ni][e] = 0.f;

#pragma unroll
        for (int kd = 0; kd < 4; kd++) {
            uint32_t kh[4][4], kl[4][4];
#pragma unroll
            for (int g = 0; g < 4; g++) {
                ldsm4(kh[g], stg + b_off + kd * 32 + g * 16 * FSTR);
                ldsm4(kl[g], stg + FOP + b_off + kd * 32 + g * 16 * FSTR);
            }
#pragma unroll
            for (int ni = 0; ni < 8; ni++) {
                const int g = ni >> 1, sel = (ni & 1) * 2;
                mma_bf16(sc[ni], qfh[kd], &kh[g][sel]);
                mma_bf16(sc[ni], qfh[kd], &kl[g][sel]);
                mma_bf16(sc[ni], qfl[kd], &kh[g][sel]);
            }
        }

        // ---- bias + causal mask ----
#pragma unroll
        for (int ni = 0; ni < 8; ni++) {
            float2 bb = *reinterpret_cast<float2*>(&biasp[s * 64 + ni * 8 + 2 * tig]);
            sc[ni][0] += bb.x; sc[ni][1] += bb.y;
            sc[ni][2] += bb.x; sc[ni][3] += bb.y;
        }
        if (krow0 + 63 > qrow0) {
            const int r0 = qrow0 + w * 16 + grp;
            const int r1 = r0 + 8;
#pragma unroll
            for (int ni = 0; ni < 8; ni++) {
                int c0 = krow0 + ni * 8 + 2 * tig;
                if (c0 > r0) sc[ni][0] = -1e30f;
                if (c0 + 1 > r0) sc[ni][1] = -1e30f;
                if (c0 > r1) sc[ni][2] = -1e30f;
                if (c0 + 1 > r1) sc[ni][3] = -1e30f;
            }
        }

        // ---- online softmax ----
        float mx0 = -1e30f, mx1 = -1e30f;
#pragma unroll
        for (int ni = 0; ni < 8; ni++) {
            mx0 = fmaxf(mx0, fmaxf(sc[ni][0], sc[ni][1]));
            mx1 = fmaxf(mx1, fmaxf(sc[ni][2], sc[ni][3]));
        }
        mx0 = fmaxf(mx0, __shfl_xor_sync(0xffffffffu, mx0, 1));
        mx0 = fmaxf(mx0, __shfl_xor_sync(0xffffffffu, mx0, 2));
        mx1 = fmaxf(mx1, __shfl_xor_sync(0xffffffffu, mx1, 1));
        mx1 = fmaxf(mx1, __shfl_xor_sync(0xffffffffu, mx1, 2));
        float mn0 = fmaxf(m0, mx0), mn1 = fmaxf(m1, mx1);
        float cr0 = fexp2((m0 - mn0) * LOG2E);
        float cr1 = fexp2((m1 - mn1) * LOG2E);
        m0 = mn0; m1 = mn1;

        uint32_t ph[8][2], pl[8][2];
        float rs0 = 0.f, rs1 = 0.f;
#pragma unroll
        for (int ni = 0; ni < 8; ni++) {
            float p0 = fexp2((sc[ni][0] - mn0) * LOG2E);
            float p1 = fexp2((sc[ni][1] - mn0) * LOG2E);
            float p2 = fexp2((sc[ni][2] - mn1) * LOG2E);
            float p3 = fexp2((sc[ni][3] - mn1) * LOG2E);
            rs0 += p0 + p1; rs1 += p2 + p3;
            split_pack(p0, p1, ph[ni][0], pl[ni][0]);
            split_pack(p2, p3, ph[ni][1], pl[ni][1]);
        }
        rs0 += __shfl_xor_sync(0xffffffffu, rs0, 1);
        rs0 += __shfl_xor_sync(0xffffffffu, rs0, 2);
        rs1 += __shfl_xor_sync(0xffffffffu, rs1, 1);
        rs1 += __shfl_xor_sync(0xffffffffu, rs1, 2);
        l0 = l0 * cr0 + rs0;
        l1 = l1 * cr1 + rs1;
#pragma unroll
        for (int ni = 0; ni < 8; ni++) {
            o[ni][0] *= cr0; o[ni][1] *= cr0;
            o[ni][2] *= cr1; o[ni][3] *= cr1;
        }

        // ---- O += P V (hi/lo x3), Vt stored [dh][kv] ----
#pragma unroll
        for (int kc = 0; kc < 4; kc++) {
            uint32_t vh[4][4], vl[4][4];
#pragma unroll
            for (int g = 0; g < 4; g++) {
                ldsm4(vh[g], stg + 2 * FOP + b_off + kc * 32 + g * 16 * FSTR);
                ldsm4(vl[g], stg + 3 * FOP + b_off + kc * 32 + g * 16 * FSTR);
            }
            uint32_t ah[4] = {ph[2 * kc][0], ph[2 * kc][1],
                              ph[2 * kc + 1][0], ph[2 * kc + 1][1]};
            uint32_t al[4] = {pl[2 * kc][0], pl[2 * kc][1],
                              pl[2 * kc + 1][0], pl[2 * kc + 1][1]};
#pragma unroll
            for (int ni = 0; ni < 8; ni++) {
                const int g = ni >> 1, sel = (ni & 1) * 2;
                mma_bf16(o[ni], ah, &vh[g][sel]);
                mma_bf16(o[ni], ah, &vl[g][sel]);
                mma_bf16(o[ni], al, &vh[g][sel]);
            }
        }
        __syncthreads();
    }

    // ---- epilogue: /l, query padding, write bf16 hi/lo to [B*T, D] ----
    const int r0 = qrow0 + w * 16 + grp;
    const int r1 = r0 + 8;
    float f0 = (l0 > 0.f ? 1.0f / l0 : 0.f) * (float)qpm[b * SEQ + r0];
    float f1 = (l1 > 0.f ? 1.0f / l1 : 0.f) * (float)qpm[b * SEQ + r1];
#pragma unroll
    for (int ni = 0; ni < 8; ni++) {
        int col = h * HD + ni * 8 + 2 * tig;
        uint32_t hw, lw;
        split_pack(o[ni][0] * f0, o[ni][1] * f0, hw, lw);
        size_t i0 = (size_t)(b * SEQ + r0) * DM + col;
        *reinterpret_cast<uint32_t*>(g_aoh + i0) = hw;
        *reinterpret_cast<uint32_t*>(g_aol + i0) = lw;
        split_pack(o[ni][2] * f1, o[ni][3] * f1, hw, lw);
        size_t i1 = (size_t)(b * SEQ + r1) * DM + col;
        *reinterpret_cast<uint32_t*>(g_aoh + i1) = hw;
        *reinterpret_cast<uint32_t*>(g_aol + i1) = lw;
    }
}

// ---------------- launch -----------------------------------------------------
extern "C" void kernel_launch(void* const* d_in, const int* in_sizes, int n_in,
                              void* d_out, int out_size) {
    const float* q   = (const float*)d_in[0];
    const float* k   = (const float*)d_in[1];
    const float* v   = (const float*)d_in[2];
    const int*   qpm = (const int*)d_in[3];
    const int*   kpm = (const int*)d_in[4];
    const float* Wq  = (const float*)d_in[5];
    const float* Wk  = (const float*)d_in[6];
    const float* Wv  = (const float*)d_in[7];
    const float* Wo  = (const float*)d_in[8];
    float* out = (float*)d_out;

    dim3 gs((MTOT * DM) / (256 * 4), 1, 3);
    split_act_kernel<<<gs, 256>>>(q, k, v);
    split_w_kernel<<<dim3(32, 32, 4), 256>>>(Wq, Wk, Wv, Wo);

    cudaFuncSetAttribute(gemm_qkv_kernel,
                         cudaFuncAttributeMaxDynamicSharedMemorySize, GEMM_SMEM);
    cudaFuncSetAttribute(gemm_o_kernel,
                         cudaFuncAttributeMaxDynamicSharedMemorySize, GEMM_SMEM);
    gemm_qkv_kernel<<<dim3(DM / 128, MTOT / 128, 3), 256, GEMM_SMEM>>>();

    cudaFuncSetAttribute(flash_kernel,
                         cudaFuncAttributeMaxDynamicSharedMemorySize, FLASH_SMEM);
    flash_kernel<<<dim3(SEQ / 128, NB * NH), 256, FLASH_SMEM>>>(qpm, kpm);

    gemm_o_kernel<<<dim3(DM / 128, MTOT / 128), 256, GEMM_SMEM>>>(out);
}